// round 5
// baseline (speedup 1.0000x reference)
#include <cuda_runtime.h>
#include <cuda_bf16.h>
#include <math.h>
#include <stdint.h>

// Problem dims (fixed by the dataset)
#define BATCH   32
#define STEPS   1024      // T
#define HD      1024      // D == H
#define BT      32768     // BATCH*STEPS rows
#define NCTA    128       // scan grid (all co-resident, 1 CTA/SM)
#define SCAN_THREADS 256

// ---------------- scratch (no allocations allowed) ----------------
__device__ float         g_xproj[(size_t)BT * HD];     // 128 MB input-proj result
__device__ float         g_hbuf[2][HD * BATCH];        // h double buffer, [o][b] layout
__device__ unsigned int  g_bar[STEPS];                 // per-step grid barrier counters
__device__ __nv_bfloat16 g_Ahi[(size_t)BT * HD];       // 64 MB
__device__ __nv_bfloat16 g_Alo[(size_t)BT * HD];       // 64 MB
__device__ __nv_bfloat16 g_Bhi[HD * HD];               // 2 MB
__device__ __nv_bfloat16 g_Blo[HD * HD];               // 2 MB

// =================================================================
// helpers (plain sm_80-era PTX + base-sm_100 f32x2)
// =================================================================
__device__ __forceinline__ uint32_t smem_u32(const void* p) {
    uint32_t a;
    asm("{ .reg .u64 t; cvta.to.shared.u64 t, %1; cvt.u32.u64 %0, t; }" : "=r"(a) : "l"(p));
    return a;
}
__device__ __forceinline__ void cp_async16(uint32_t dst, const void* src) {
    asm volatile("cp.async.cg.shared.global [%0], [%1], 16;" :: "r"(dst), "l"(src));
}
__device__ __forceinline__ void cp_commit() {
    asm volatile("cp.async.commit_group;");
}
__device__ __forceinline__ void cp_wait1() {
    asm volatile("cp.async.wait_group 1;");
}
__device__ __forceinline__ void ldsm_x4(uint32_t* r, uint32_t addr) {
    asm volatile("ldmatrix.sync.aligned.m8n8.x4.shared.b16 {%0,%1,%2,%3}, [%4];"
                 : "=r"(r[0]), "=r"(r[1]), "=r"(r[2]), "=r"(r[3]) : "r"(addr));
}
__device__ __forceinline__ void mma_bf16(float* c, const uint32_t* a, const uint32_t* b) {
    asm volatile(
        "mma.sync.aligned.m16n8k16.row.col.f32.bf16.bf16.f32 "
        "{%0,%1,%2,%3}, {%4,%5,%6,%7}, {%8,%9}, {%0,%1,%2,%3};"
        : "+f"(c[0]), "+f"(c[1]), "+f"(c[2]), "+f"(c[3])
        : "r"(a[0]), "r"(a[1]), "r"(a[2]), "r"(a[3]), "r"(b[0]), "r"(b[1]));
}
// packed fp32 pair FMA (Blackwell base feature, PTX ISA 8.6+)
__device__ __forceinline__ unsigned long long pack2(float x, float y) {
    unsigned long long r;
    asm("mov.b64 %0, {%1, %2};" : "=l"(r) : "f"(x), "f"(y));
    return r;
}
__device__ __forceinline__ void fma2(unsigned long long& d, unsigned long long a,
                                     unsigned long long b) {
    asm("fma.rn.f32x2 %0, %1, %2, %0;" : "+l"(d) : "l"(a), "l"(b));
}

// =================================================================
// split fp32 -> bf16 hi + bf16 lo
// =================================================================
__global__ void split_bf16(const float* __restrict__ in,
                           __nv_bfloat16* __restrict__ hi,
                           __nv_bfloat16* __restrict__ lo, int n4) {
    int i = blockIdx.x * blockDim.x + threadIdx.x;
    if (i >= n4) return;
    float4 v = ((const float4*)in)[i];
    __nv_bfloat16 h0 = __float2bfloat16(v.x);
    __nv_bfloat16 h1 = __float2bfloat16(v.y);
    __nv_bfloat16 h2 = __float2bfloat16(v.z);
    __nv_bfloat16 h3 = __float2bfloat16(v.w);
    __nv_bfloat16 l0 = __float2bfloat16(v.x - __bfloat162float(h0));
    __nv_bfloat16 l1 = __float2bfloat16(v.y - __bfloat162float(h1));
    __nv_bfloat16 l2 = __float2bfloat16(v.z - __bfloat162float(h2));
    __nv_bfloat16 l3 = __float2bfloat16(v.w - __bfloat162float(h3));
    ((__nv_bfloat162*)hi)[2 * i + 0] = __halves2bfloat162(h0, h1);
    ((__nv_bfloat162*)hi)[2 * i + 1] = __halves2bfloat162(h2, h3);
    ((__nv_bfloat162*)lo)[2 * i + 0] = __halves2bfloat162(l0, l1);
    ((__nv_bfloat162*)lo)[2 * i + 1] = __halves2bfloat162(l2, l3);
}

// =================================================================
// HMMA split-bf16 GEMM (NT)  -- unchanged from R4 (passing)
// =================================================================
#define GSTAGES 3
#define TILE_B   10240
#define STAGE_B  (4 * TILE_B)
#define ROWB     80

__global__ __launch_bounds__(256)
void mma_gemm(const __nv_bfloat16* __restrict__ Ahi, const __nv_bfloat16* __restrict__ Alo,
              const __nv_bfloat16* __restrict__ Bhi, const __nv_bfloat16* __restrict__ Blo,
              const float* __restrict__ bias, float* __restrict__ C) {
    extern __shared__ char dsm[];
    const uint32_t sb = smem_u32(dsm);

    const int tid = threadIdx.x;
    const int wid = tid >> 5;
    const int lane = tid & 31;
    const int bm = blockIdx.y * 128;
    const int bn = blockIdx.x * 128;
    const int wm = (wid >> 2) * 64;
    const int wn = (wid & 3) * 32;

    const int lt  = tid >> 6;
    const int lid = tid & 63;
    const __nv_bfloat16* lsrc = (lt == 0) ? Ahi : (lt == 1) ? Alo : (lt == 2) ? Bhi : Blo;
    const int lrowb = (lt < 2) ? bm : bn;

    float acc[4][4][4];
#pragma unroll
    for (int i = 0; i < 4; i++)
#pragma unroll
        for (int j = 0; j < 4; j++)
#pragma unroll
            for (int e = 0; e < 4; e++) acc[i][j][e] = 0.f;

#pragma unroll
    for (int ps = 0; ps < GSTAGES - 1; ps++) {
        uint32_t dstb = sb + ps * STAGE_B + lt * TILE_B;
#pragma unroll
        for (int i = 0; i < 8; i++) {
            int idx = i * 64 + lid;
            int r = idx >> 2, c = idx & 3;
            cp_async16(dstb + r * ROWB + c * 16,
                       lsrc + (size_t)(lrowb + r) * HD + ps * 32 + c * 8);
        }
        cp_commit();
    }

    for (int kt = 0; kt < HD / 32; kt++) {
        cp_wait1();
        __syncthreads();

        if (kt + GSTAGES - 1 < HD / 32) {
            uint32_t dstb = sb + ((kt + GSTAGES - 1) % GSTAGES) * STAGE_B + lt * TILE_B;
#pragma unroll
            for (int i = 0; i < 8; i++) {
                int idx = i * 64 + lid;
                int r = idx >> 2, c = idx & 3;
                cp_async16(dstb + r * ROWB + c * 16,
                           lsrc + (size_t)(lrowb + r) * HD + (kt + GSTAGES - 1) * 32 + c * 8);
            }
        }
        cp_commit();

        uint32_t stg = sb + (kt % GSTAGES) * STAGE_B;
        uint32_t aBaseH = stg + 0 * TILE_B;
        uint32_t aBaseL = stg + 1 * TILE_B;
        uint32_t bBaseH = stg + 2 * TILE_B;
        uint32_t bBaseL = stg + 3 * TILE_B;

#pragma unroll
        for (int ks = 0; ks < 2; ks++) {
            uint32_t ah[4][4], al[4][4], bh[4][2], bl[4][2];
            int arow = (lane & 15);
            int acol = (lane >> 4) * 16 + ks * 32;
#pragma unroll
            for (int mt = 0; mt < 4; mt++) {
                ldsm_x4(ah[mt], aBaseH + (wm + mt * 16 + arow) * ROWB + acol);
                ldsm_x4(al[mt], aBaseL + (wm + mt * 16 + arow) * ROWB + acol);
            }
            int brow = ((lane >> 4) << 3) + (lane & 7);
            int bcol = ((lane >> 3) & 1) * 16 + ks * 32;
#pragma unroll
            for (int p = 0; p < 2; p++) {
                uint32_t t[4];
                ldsm_x4(t, bBaseH + (wn + p * 16 + brow) * ROWB + bcol);
                bh[2 * p][0] = t[0]; bh[2 * p][1] = t[1];
                bh[2 * p + 1][0] = t[2]; bh[2 * p + 1][1] = t[3];
                ldsm_x4(t, bBaseL + (wn + p * 16 + brow) * ROWB + bcol);
                bl[2 * p][0] = t[0]; bl[2 * p][1] = t[1];
                bl[2 * p + 1][0] = t[2]; bl[2 * p + 1][1] = t[3];
            }
#pragma unroll
            for (int mt = 0; mt < 4; mt++)
#pragma unroll
                for (int nt = 0; nt < 4; nt++) {
                    mma_bf16(acc[mt][nt], ah[mt], bh[nt]);
                    mma_bf16(acc[mt][nt], ah[mt], bl[nt]);
                    mma_bf16(acc[mt][nt], al[mt], bh[nt]);
                }
        }
    }

#pragma unroll
    for (int mt = 0; mt < 4; mt++) {
#pragma unroll
        for (int nt = 0; nt < 4; nt++) {
            int m0 = bm + wm + mt * 16 + (lane >> 2);
            int n0 = bn + wn + nt * 8 + (lane & 3) * 2;
            float b0 = bias[n0], b1 = bias[n0 + 1];
            float2 v0 = make_float2(acc[mt][nt][0] + b0, acc[mt][nt][1] + b1);
            float2 v1 = make_float2(acc[mt][nt][2] + b0, acc[mt][nt][3] + b1);
            *(float2*)&C[(size_t)m0 * HD + n0] = v0;
            *(float2*)&C[(size_t)(m0 + 8) * HD + n0] = v1;
        }
    }
}

// =================================================================
// Persistent recurrent scan v2:
//  - f32x2 packed FMA compute, 8b x 4o register tiles
//  - k strided by 32 per thread (bank-conflict-free with 144B sH rows)
//  - h broadcast staged via cp.async in 4 chunks, overlapped with compute
//  - release/acquire grid barrier
//  - emits hidden (fp32) AND its bf16 hi/lo split for the output GEMM
// =================================================================
__device__ __forceinline__ float gelu_exact(float x) {
    return 0.5f * x * (1.0f + erff(x * 0.70710678118654752f));
}

#define SH_STRIDE 36      // floats per k-row of sH (144B: 32 b + pad)
#define SP_STRIDE 258     // floats per kc-row of sPart (1032B)
// smem floats: sWh 8192 | sH 36864 | sPart 8256  -> 53312 floats = 213248 B

extern __shared__ float s_mem[];

__global__ __launch_bounds__(SCAN_THREADS)
void scan_kernel(const float* __restrict__ xproj,
                 const float* __restrict__ Wh,
                 float* __restrict__ hidden,
                 __nv_bfloat16* __restrict__ hhi,
                 __nv_bfloat16* __restrict__ hlo) {
    float* sWh   = s_mem;                 // [k][o(8)]  32B rows
    float* sH    = s_mem + 8192;          // [k][b(32)+pad] 144B rows
    float* sPart = s_mem + 8192 + 36864;  // [kc(32)][256+pad]

    const int tid = threadIdx.x;
    const int o_base = blockIdx.x * 8;

    // load Wh slice: sWh[k*8 + o] = Wh[(o_base+o)*HD + k]
    const float4* Wh4 = (const float4*)Wh;
    for (int idx = tid; idx < 2048; idx += SCAN_THREADS) {
        int o = idx >> 8;
        int k4 = idx & 255;
        float4 w = Wh4[(o_base + o) * 256 + k4];
        int k = k4 << 2;
        sWh[(k + 0) * 8 + o] = w.x;
        sWh[(k + 1) * 8 + o] = w.y;
        sWh[(k + 2) * 8 + o] = w.z;
        sWh[(k + 3) * 8 + o] = w.w;
    }
    // zero sH (h0 = 0)
    {
        float4* z = (float4*)sH;
        float4 z4 = make_float4(0.f, 0.f, 0.f, 0.f);
        for (int i = tid; i < 9216; i += SCAN_THREADS) z[i] = z4;
    }

    // compute mapping: kc = k-offset (stride-32 chunks), tile -> (bg, og)
    const int kc = tid >> 3;              // 0..31
    const int tile = tid & 7;             // 0..7
    const int bg = tile >> 1;             // 0..3 (8 batches each)
    const int og = tile & 1;              // 0..1 (4 outputs each)

    const float* hRow = sH + bg * 8;
    const float* wRow = sWh + og * 4;
    const uint32_t sH_u32 = smem_u32(sH);

    // reduce mapping: out = tid (b-major: b = tid>>3, o = tid&7)
    const int rb = tid >> 3;
    const int ro = tid & 7;

    float xv = xproj[(rb * STEPS + 0) * HD + o_base + ro];

    for (int s = 0; s < STEPS; s++) {
        // ---- stage h_{s} (from step s-1) in 4 chunks of 256 k-rows ----
        if (s > 0) {
            const float4* src = (const float4*)g_hbuf[(s - 1) & 1];
#pragma unroll
            for (int c = 0; c < 4; c++) {
                int base = c * 2048 + tid * 8;
#pragma unroll
                for (int q = 0; q < 8; q++) {
                    int idx = base + q;
                    int k = idx >> 3, b4 = idx & 7;
                    cp_async16(sH_u32 + k * 144 + b4 * 16, src + idx);
                }
                cp_commit();
            }
        }

        // ---- compute: acc{b,b+1}[o] += h-pair * {w,w}, chunk-pipelined ----
        unsigned long long acc[4][4];
#pragma unroll
        for (int bp = 0; bp < 4; bp++)
#pragma unroll
            for (int oi = 0; oi < 4; oi++) acc[bp][oi] = 0ull;

#pragma unroll
        for (int c = 0; c < 4; c++) {
            if (s > 0) {
                if (c == 0)      asm volatile("cp.async.wait_group 3;");
                else if (c == 1) asm volatile("cp.async.wait_group 2;");
                else if (c == 2) asm volatile("cp.async.wait_group 1;");
                else             asm volatile("cp.async.wait_group 0;");
            }
            __syncthreads();
#pragma unroll
            for (int jj = 0; jj < 8; jj++) {
                int k = kc + (c * 8 + jj) * 32;
                ulonglong2 h01 = *(const ulonglong2*)(hRow + k * SH_STRIDE);
                ulonglong2 h23 = *(const ulonglong2*)(hRow + k * SH_STRIDE + 4);
                float4 wv = *(const float4*)(wRow + k * 8);
                unsigned long long w0 = pack2(wv.x, wv.x);
                unsigned long long w1 = pack2(wv.y, wv.y);
                unsigned long long w2 = pack2(wv.z, wv.z);
                unsigned long long w3 = pack2(wv.w, wv.w);
                fma2(acc[0][0], h01.x, w0); fma2(acc[0][1], h01.x, w1);
                fma2(acc[0][2], h01.x, w2); fma2(acc[0][3], h01.x, w3);
                fma2(acc[1][0], h01.y, w0); fma2(acc[1][1], h01.y, w1);
                fma2(acc[1][2], h01.y, w2); fma2(acc[1][3], h01.y, w3);
                fma2(acc[2][0], h23.x, w0); fma2(acc[2][1], h23.x, w1);
                fma2(acc[2][2], h23.x, w2); fma2(acc[2][3], h23.x, w3);
                fma2(acc[3][0], h23.y, w0); fma2(acc[3][1], h23.y, w1);
                fma2(acc[3][2], h23.y, w2); fma2(acc[3][3], h23.y, w3);
            }
        }

        // ---- write partials ----
        {
            float* pr = sPart + kc * SP_STRIDE;
#pragma unroll
            for (int bp = 0; bp < 4; bp++)
#pragma unroll
                for (int oi = 0; oi < 4; oi++) {
                    union { unsigned long long u; float2 f; } v;
                    v.u = acc[bp][oi];
                    int out0 = (bg * 8 + bp * 2) * 8 + og * 4 + oi;
                    pr[out0] = v.f.x;
                    pr[out0 + 8] = v.f.y;
                }
        }
        __syncthreads();

        // ---- reduce K-split partials, add x_t, GELU ----
        float v = 0.f;
#pragma unroll
        for (int q = 0; q < 32; q++)
            v += sPart[q * SP_STRIDE + tid];
        v += xv;
        float hval = gelu_exact(v);

        size_t hidx = (size_t)(rb * STEPS + s) * HD + o_base + ro;
        hidden[hidx] = hval;
        __nv_bfloat16 bhi = __float2bfloat16(hval);
        hhi[hidx] = bhi;
        hlo[hidx] = __float2bfloat16(hval - __bfloat162float(bhi));
        g_hbuf[s & 1][(o_base + ro) * BATCH + rb] = hval;

        __syncthreads();   // all h stores happen-before the release arrive

        if (tid == 0)
            asm volatile("red.release.gpu.global.add.u32 [%0], %1;"
                         :: "l"(&g_bar[s]), "r"(1u) : "memory");

        // prefetch next step's xproj while the barrier fills
        float xnext = 0.f;
        if (s + 1 < STEPS)
            xnext = xproj[(rb * STEPS + s + 1) * HD + o_base + ro];

        if (tid == 0) {
            unsigned int cnt;
            do {
                asm volatile("ld.acquire.gpu.global.u32 %0, [%1];"
                             : "=r"(cnt) : "l"(&g_bar[s]) : "memory");
            } while (cnt < NCTA);
        }
        __syncthreads();   // barrier passed for the whole CTA

        xv = xnext;
    }
}

// =================================================================
extern "C" void kernel_launch(void* const* d_in, const int* in_sizes, int n_in,
                              void* d_out, int out_size) {
    const float* seq = (const float*)d_in[0];   // (B,T,D)
    const float* Wi  = (const float*)d_in[1];   // (H,D)
    const float* bi  = (const float*)d_in[2];   // (H,)
    const float* Wh  = (const float*)d_in[3];   // (H,H)
    const float* Wo  = (const float*)d_in[4];   // (H,H)
    const float* bo  = (const float*)d_in[5];   // (H,)

    float* out     = (float*)d_out;
    float* hidden  = out;                          // (B,T,H)
    float* outproj = out + (size_t)BT * HD;        // (B,T,H)

    void *xp_addr = 0, *bar_addr = 0, *ahi = 0, *alo = 0, *bhi = 0, *blo = 0;
    cudaGetSymbolAddress(&xp_addr, g_xproj);
    cudaGetSymbolAddress(&bar_addr, g_bar);
    cudaGetSymbolAddress(&ahi, g_Ahi);
    cudaGetSymbolAddress(&alo, g_Alo);
    cudaGetSymbolAddress(&bhi, g_Bhi);
    cudaGetSymbolAddress(&blo, g_Blo);

    cudaMemsetAsync(bar_addr, 0, STEPS * sizeof(unsigned int));

    const int nA4 = BT * HD / 4;       // 8388608
    const int nW4 = HD * HD / 4;       // 262144
    const int gemm_smem = GSTAGES * STAGE_B;   // 122880
    cudaFuncSetAttribute(mma_gemm, cudaFuncAttributeMaxDynamicSharedMemorySize, gemm_smem);
    dim3 ggrid(HD / 128, BT / 128);    // (8, 256)

    // 1) input projection: xproj = seq @ Wi^T + bi  (split-bf16 HMMA)
    split_bf16<<<nA4 / 256, 256>>>(seq, (__nv_bfloat16*)ahi, (__nv_bfloat16*)alo, nA4);
    split_bf16<<<nW4 / 256, 256>>>(Wi, (__nv_bfloat16*)bhi, (__nv_bfloat16*)blo, nW4);
    mma_gemm<<<ggrid, 256, gemm_smem>>>((const __nv_bfloat16*)ahi, (const __nv_bfloat16*)alo,
                                        (const __nv_bfloat16*)bhi, (const __nv_bfloat16*)blo,
                                        bi, (float*)xp_addr);

    // 2) recurrent scan (persistent, grid-synchronized, f32x2 compute)
    const int scan_smem = (8192 + 36864 + 32 * SP_STRIDE) * (int)sizeof(float);  // 213248
    cudaFuncSetAttribute(scan_kernel, cudaFuncAttributeMaxDynamicSharedMemorySize, scan_smem);
    scan_kernel<<<NCTA, SCAN_THREADS, scan_smem>>>((const float*)xp_addr, Wh, hidden,
                                                   (__nv_bfloat16*)ahi, (__nv_bfloat16*)alo);

    // 3) output projection: out = hidden @ Wo^T + bo  (hi/lo already emitted by scan)
    split_bf16<<<nW4 / 256, 256>>>(Wo, (__nv_bfloat16*)bhi, (__nv_bfloat16*)blo, nW4);
    mma_gemm<<<ggrid, 256, gemm_smem>>>((const __nv_bfloat16*)ahi, (const __nv_bfloat16*)alo,
                                        (const __nv_bfloat16*)bhi, (const __nv_bfloat16*)blo,
                                        bo, outproj);
}

// round 6
// speedup vs baseline: 1.3625x; 1.3625x over previous
#include <cuda_runtime.h>
#include <cuda_bf16.h>
#include <math.h>
#include <stdint.h>

// Problem dims (fixed by the dataset)
#define BATCH   32
#define STEPS   1024      // T
#define HD      1024      // D == H
#define BT      32768     // BATCH*STEPS rows
#define NCTA    128       // scan grid (all co-resident, 1 CTA/SM)
#define SCAN_THREADS 512

// ---------------- scratch (no allocations allowed) ----------------
__device__ float         g_xproj[(size_t)BT * HD];     // 128 MB input-proj result
__device__ float         g_hbuf[2][HD * BATCH];        // h double buffer, [o][b] layout
__device__ unsigned int  g_bar[STEPS];                 // per-step grid barrier counters
__device__ __nv_bfloat16 g_Ahi[(size_t)BT * HD];       // 64 MB
__device__ __nv_bfloat16 g_Alo[(size_t)BT * HD];       // 64 MB
__device__ __nv_bfloat16 g_Bhi[HD * HD];               // 2 MB
__device__ __nv_bfloat16 g_Blo[HD * HD];               // 2 MB

// =================================================================
// helpers (plain sm_80-era PTX + base-sm_100 f32x2)
// =================================================================
__device__ __forceinline__ uint32_t smem_u32(const void* p) {
    uint32_t a;
    asm("{ .reg .u64 t; cvta.to.shared.u64 t, %1; cvt.u32.u64 %0, t; }" : "=r"(a) : "l"(p));
    return a;
}
__device__ __forceinline__ void cp_async16(uint32_t dst, const void* src) {
    asm volatile("cp.async.cg.shared.global [%0], [%1], 16;" :: "r"(dst), "l"(src));
}
__device__ __forceinline__ void cp_commit() {
    asm volatile("cp.async.commit_group;");
}
__device__ __forceinline__ void cp_wait1() {
    asm volatile("cp.async.wait_group 1;");
}
__device__ __forceinline__ void ldsm_x4(uint32_t* r, uint32_t addr) {
    asm volatile("ldmatrix.sync.aligned.m8n8.x4.shared.b16 {%0,%1,%2,%3}, [%4];"
                 : "=r"(r[0]), "=r"(r[1]), "=r"(r[2]), "=r"(r[3]) : "r"(addr));
}
__device__ __forceinline__ void mma_bf16(float* c, const uint32_t* a, const uint32_t* b) {
    asm volatile(
        "mma.sync.aligned.m16n8k16.row.col.f32.bf16.bf16.f32 "
        "{%0,%1,%2,%3}, {%4,%5,%6,%7}, {%8,%9}, {%0,%1,%2,%3};"
        : "+f"(c[0]), "+f"(c[1]), "+f"(c[2]), "+f"(c[3])
        : "r"(a[0]), "r"(a[1]), "r"(a[2]), "r"(a[3]), "r"(b[0]), "r"(b[1]));
}
// packed fp32 pair FMA (Blackwell base feature, PTX ISA 8.6+)
__device__ __forceinline__ unsigned long long pack2(float x, float y) {
    unsigned long long r;
    asm("mov.b64 %0, {%1, %2};" : "=l"(r) : "f"(x), "f"(y));
    return r;
}
__device__ __forceinline__ void fma2(unsigned long long& d, unsigned long long a,
                                     unsigned long long b) {
    asm("fma.rn.f32x2 %0, %1, %2, %0;" : "+l"(d) : "l"(a), "l"(b));
}

// =================================================================
// split fp32 -> bf16 hi + bf16 lo
// =================================================================
__global__ void split_bf16(const float* __restrict__ in,
                           __nv_bfloat16* __restrict__ hi,
                           __nv_bfloat16* __restrict__ lo, int n4) {
    int i = blockIdx.x * blockDim.x + threadIdx.x;
    if (i >= n4) return;
    float4 v = ((const float4*)in)[i];
    __nv_bfloat16 h0 = __float2bfloat16(v.x);
    __nv_bfloat16 h1 = __float2bfloat16(v.y);
    __nv_bfloat16 h2 = __float2bfloat16(v.z);
    __nv_bfloat16 h3 = __float2bfloat16(v.w);
    __nv_bfloat16 l0 = __float2bfloat16(v.x - __bfloat162float(h0));
    __nv_bfloat16 l1 = __float2bfloat16(v.y - __bfloat162float(h1));
    __nv_bfloat16 l2 = __float2bfloat16(v.z - __bfloat162float(h2));
    __nv_bfloat16 l3 = __float2bfloat16(v.w - __bfloat162float(h3));
    ((__nv_bfloat162*)hi)[2 * i + 0] = __halves2bfloat162(h0, h1);
    ((__nv_bfloat162*)hi)[2 * i + 1] = __halves2bfloat162(h2, h3);
    ((__nv_bfloat162*)lo)[2 * i + 0] = __halves2bfloat162(l0, l1);
    ((__nv_bfloat162*)lo)[2 * i + 1] = __halves2bfloat162(l2, l3);
}

// =================================================================
// HMMA split-bf16 GEMM (NT)  -- unchanged (passing since R4)
// =================================================================
#define GSTAGES 3
#define TILE_B   10240
#define STAGE_B  (4 * TILE_B)
#define ROWB     80

__global__ __launch_bounds__(256)
void mma_gemm(const __nv_bfloat16* __restrict__ Ahi, const __nv_bfloat16* __restrict__ Alo,
              const __nv_bfloat16* __restrict__ Bhi, const __nv_bfloat16* __restrict__ Blo,
              const float* __restrict__ bias, float* __restrict__ C) {
    extern __shared__ char dsm[];
    const uint32_t sb = smem_u32(dsm);

    const int tid = threadIdx.x;
    const int wid = tid >> 5;
    const int lane = tid & 31;
    const int bm = blockIdx.y * 128;
    const int bn = blockIdx.x * 128;
    const int wm = (wid >> 2) * 64;
    const int wn = (wid & 3) * 32;

    const int lt  = tid >> 6;
    const int lid = tid & 63;
    const __nv_bfloat16* lsrc = (lt == 0) ? Ahi : (lt == 1) ? Alo : (lt == 2) ? Bhi : Blo;
    const int lrowb = (lt < 2) ? bm : bn;

    float acc[4][4][4];
#pragma unroll
    for (int i = 0; i < 4; i++)
#pragma unroll
        for (int j = 0; j < 4; j++)
#pragma unroll
            for (int e = 0; e < 4; e++) acc[i][j][e] = 0.f;

#pragma unroll
    for (int ps = 0; ps < GSTAGES - 1; ps++) {
        uint32_t dstb = sb + ps * STAGE_B + lt * TILE_B;
#pragma unroll
        for (int i = 0; i < 8; i++) {
            int idx = i * 64 + lid;
            int r = idx >> 2, c = idx & 3;
            cp_async16(dstb + r * ROWB + c * 16,
                       lsrc + (size_t)(lrowb + r) * HD + ps * 32 + c * 8);
        }
        cp_commit();
    }

    for (int kt = 0; kt < HD / 32; kt++) {
        cp_wait1();
        __syncthreads();

        if (kt + GSTAGES - 1 < HD / 32) {
            uint32_t dstb = sb + ((kt + GSTAGES - 1) % GSTAGES) * STAGE_B + lt * TILE_B;
#pragma unroll
            for (int i = 0; i < 8; i++) {
                int idx = i * 64 + lid;
                int r = idx >> 2, c = idx & 3;
                cp_async16(dstb + r * ROWB + c * 16,
                           lsrc + (size_t)(lrowb + r) * HD + (kt + GSTAGES - 1) * 32 + c * 8);
            }
        }
        cp_commit();

        uint32_t stg = sb + (kt % GSTAGES) * STAGE_B;
        uint32_t aBaseH = stg + 0 * TILE_B;
        uint32_t aBaseL = stg + 1 * TILE_B;
        uint32_t bBaseH = stg + 2 * TILE_B;
        uint32_t bBaseL = stg + 3 * TILE_B;

#pragma unroll
        for (int ks = 0; ks < 2; ks++) {
            uint32_t ah[4][4], al[4][4], bh[4][2], bl[4][2];
            int arow = (lane & 15);
            int acol = (lane >> 4) * 16 + ks * 32;
#pragma unroll
            for (int mt = 0; mt < 4; mt++) {
                ldsm_x4(ah[mt], aBaseH + (wm + mt * 16 + arow) * ROWB + acol);
                ldsm_x4(al[mt], aBaseL + (wm + mt * 16 + arow) * ROWB + acol);
            }
            int brow = ((lane >> 4) << 3) + (lane & 7);
            int bcol = ((lane >> 3) & 1) * 16 + ks * 32;
#pragma unroll
            for (int p = 0; p < 2; p++) {
                uint32_t t[4];
                ldsm_x4(t, bBaseH + (wn + p * 16 + brow) * ROWB + bcol);
                bh[2 * p][0] = t[0]; bh[2 * p][1] = t[1];
                bh[2 * p + 1][0] = t[2]; bh[2 * p + 1][1] = t[3];
                ldsm_x4(t, bBaseL + (wn + p * 16 + brow) * ROWB + bcol);
                bl[2 * p][0] = t[0]; bl[2 * p][1] = t[1];
                bl[2 * p + 1][0] = t[2]; bl[2 * p + 1][1] = t[3];
            }
#pragma unroll
            for (int mt = 0; mt < 4; mt++)
#pragma unroll
                for (int nt = 0; nt < 4; nt++) {
                    mma_bf16(acc[mt][nt], ah[mt], bh[nt]);
                    mma_bf16(acc[mt][nt], ah[mt], bl[nt]);
                    mma_bf16(acc[mt][nt], al[mt], bh[nt]);
                }
        }
    }

#pragma unroll
    for (int mt = 0; mt < 4; mt++) {
#pragma unroll
        for (int nt = 0; nt < 4; nt++) {
            int m0 = bm + wm + mt * 16 + (lane >> 2);
            int n0 = bn + wn + nt * 8 + (lane & 3) * 2;
            float b0 = bias[n0], b1 = bias[n0 + 1];
            float2 v0 = make_float2(acc[mt][nt][0] + b0, acc[mt][nt][1] + b1);
            float2 v1 = make_float2(acc[mt][nt][2] + b0, acc[mt][nt][3] + b1);
            *(float2*)&C[(size_t)m0 * HD + n0] = v0;
            *(float2*)&C[(size_t)(m0 + 8) * HD + n0] = v1;
        }
    }
}

// =================================================================
// Persistent recurrent scan v3 (R4 skeleton, 512 threads, f32x2):
//  - 512 threads: k split 32 ways (32 k per thread), same 4b x 4o tile
//  - f32x2 packed FMA: 8 fma2 per k instead of 16 FFMA
//  - bulk __ldcg staging of h (proven R4 structure)
//  - emits hidden (fp32) AND its bf16 hi/lo split for the output GEMM
// =================================================================
__device__ __forceinline__ float gelu_exact(float x) {
    return 0.5f * x * (1.0f + erff(x * 0.70710678118654752f));
}

#define SP_STRIDE 258     // floats per kc-row of sPart (1032B)
// smem floats: sWh 8192 | sH 32768 | sPart 32*258=8256 -> 49216 floats = 196864 B

extern __shared__ float s_mem[];

__global__ __launch_bounds__(SCAN_THREADS)
void scan_kernel(const float* __restrict__ xproj,
                 const float* __restrict__ Wh,
                 float* __restrict__ hidden,
                 __nv_bfloat16* __restrict__ hhi,
                 __nv_bfloat16* __restrict__ hlo) {
    float* sWh   = s_mem;                 // [k][o(8)]
    float* sH    = s_mem + 8192;          // [k][b(32)]
    float* sPart = s_mem + 8192 + 32768;  // [kc(32)][256+pad]

    const int tid = threadIdx.x;
    const int o_base = blockIdx.x * 8;

    // load Wh slice transposed: sWh[k*8 + o] = Wh[(o_base+o)*HD + k]
    const float4* Wh4 = (const float4*)Wh;
    for (int idx = tid; idx < 2048; idx += SCAN_THREADS) {
        int o = idx >> 8;
        int k4 = idx & 255;
        float4 w = Wh4[(o_base + o) * 256 + k4];
        int k = k4 << 2;
        sWh[(k + 0) * 8 + o] = w.x;
        sWh[(k + 1) * 8 + o] = w.y;
        sWh[(k + 2) * 8 + o] = w.z;
        sWh[(k + 3) * 8 + o] = w.w;
    }
    // zero h0
    float4* sH4 = (float4*)sH;
    float4 z4 = make_float4(0.f, 0.f, 0.f, 0.f);
    for (int i = tid; i < 8192; i += SCAN_THREADS) sH4[i] = z4;

    // compute mapping: thread = (kc, bq, oq); 32 k per thread
    const int kc   = tid >> 4;           // 0..31
    const int tile = tid & 15;           // 0..15
    const int bq   = tile >> 1;          // 0..7
    const int oq   = tile & 1;           // 0..1

    // reduce mapping: out = tid>>1 (b-major), half = tid&1 sums 16 partials
    const int out  = tid >> 1;           // 0..255
    const int half = tid & 1;
    const int rb   = out >> 3;
    const int ro   = out & 7;

    const float* hp = sH + bq * 4;
    const float* wp = sWh + oq * 4;
    const int kb = kc * 32;

    float xv = (half == 0) ? xproj[(rb * STEPS + 0) * HD + o_base + ro] : 0.f;

    for (int s = 0; s < STEPS; s++) {
        __syncthreads();   // staged h_{s-1} visible

        // acc pairs: accP[p][oi] lanes = (b=bq*4+2p, b+1)
        unsigned long long accP[2][4];
#pragma unroll
        for (int p = 0; p < 2; p++)
#pragma unroll
            for (int oi = 0; oi < 4; oi++) accP[p][oi] = 0ull;

#pragma unroll 8
        for (int j = 0; j < 32; j++) {
            int k = kb + j;
            float4 hv = *(const float4*)(hp + k * 32);
            float4 wv = *(const float4*)(wp + k * 8);
            unsigned long long h01 = pack2(hv.x, hv.y);
            unsigned long long h23 = pack2(hv.z, hv.w);
            unsigned long long w0 = pack2(wv.x, wv.x);
            unsigned long long w1 = pack2(wv.y, wv.y);
            unsigned long long w2 = pack2(wv.z, wv.z);
            unsigned long long w3 = pack2(wv.w, wv.w);
            fma2(accP[0][0], h01, w0); fma2(accP[0][1], h01, w1);
            fma2(accP[0][2], h01, w2); fma2(accP[0][3], h01, w3);
            fma2(accP[1][0], h23, w0); fma2(accP[1][1], h23, w1);
            fma2(accP[1][2], h23, w2); fma2(accP[1][3], h23, w3);
        }

        // write partials: sPart[kc][ (bq*4+bi)*8 + oq*4+oi ]
        {
            float* pr = sPart + kc * SP_STRIDE + bq * 32 + oq * 4;
#pragma unroll
            for (int p = 0; p < 2; p++)
#pragma unroll
                for (int oi = 0; oi < 4; oi++) {
                    union { unsigned long long u; float2 f; } v;
                    v.u = accP[p][oi];
                    pr[(2 * p) * 8 + oi] = v.f.x;
                    pr[(2 * p + 1) * 8 + oi] = v.f.y;
                }
        }
        __syncthreads();

        // reduce 32 K-split partials (2 threads/output, 16 each + shfl)
        float v = 0.f;
#pragma unroll
        for (int q = 0; q < 16; q++)
            v += sPart[(half * 16 + q) * SP_STRIDE + out];
        v += __shfl_xor_sync(0xFFFFFFFFu, v, 1);

        if (half == 0) {
            v += xv;
            float hval = gelu_exact(v);
            size_t hidx = (size_t)(rb * STEPS + s) * HD + o_base + ro;
            hidden[hidx] = hval;
            __nv_bfloat16 bh = __float2bfloat16(hval);
            hhi[hidx] = bh;
            hlo[hidx] = __float2bfloat16(hval - __bfloat162float(bh));
            g_hbuf[s & 1][(o_base + ro) * BATCH + rb] = hval;
        }
        __threadfence();
        __syncthreads();   // all h stores fenced before arrival

        if (tid == 0) atomicAdd(&g_bar[s], 1u);   // arrive early

        // prefetch next step's xproj while the barrier fills
        float xnext = 0.f;
        if (half == 0 && s + 1 < STEPS)
            xnext = xproj[(rb * STEPS + s + 1) * HD + o_base + ro];

        if (tid == 0) {
            while (((volatile unsigned int*)g_bar)[s] < NCTA) { }
        }
        __syncthreads();

        // stage h_s: [o][b] global == [k][b] smem, straight bulk copy
        const float4* hb4 = (const float4*)g_hbuf[s & 1];
        for (int i = tid; i < 8192; i += SCAN_THREADS)
            sH4[i] = __ldcg(hb4 + i);

        xv = xnext;
    }
}

// =================================================================
extern "C" void kernel_launch(void* const* d_in, const int* in_sizes, int n_in,
                              void* d_out, int out_size) {
    const float* seq = (const float*)d_in[0];   // (B,T,D)
    const float* Wi  = (const float*)d_in[1];   // (H,D)
    const float* bi  = (const float*)d_in[2];   // (H,)
    const float* Wh  = (const float*)d_in[3];   // (H,H)
    const float* Wo  = (const float*)d_in[4];   // (H,H)
    const float* bo  = (const float*)d_in[5];   // (H,)

    float* out     = (float*)d_out;
    float* hidden  = out;                          // (B,T,H)
    float* outproj = out + (size_t)BT * HD;        // (B,T,H)

    void *xp_addr = 0, *bar_addr = 0, *ahi = 0, *alo = 0, *bhi = 0, *blo = 0;
    cudaGetSymbolAddress(&xp_addr, g_xproj);
    cudaGetSymbolAddress(&bar_addr, g_bar);
    cudaGetSymbolAddress(&ahi, g_Ahi);
    cudaGetSymbolAddress(&alo, g_Alo);
    cudaGetSymbolAddress(&bhi, g_Bhi);
    cudaGetSymbolAddress(&blo, g_Blo);

    cudaMemsetAsync(bar_addr, 0, STEPS * sizeof(unsigned int));

    const int nA4 = BT * HD / 4;       // 8388608
    const int nW4 = HD * HD / 4;       // 262144
    const int gemm_smem = GSTAGES * STAGE_B;   // 122880
    cudaFuncSetAttribute(mma_gemm, cudaFuncAttributeMaxDynamicSharedMemorySize, gemm_smem);
    dim3 ggrid(HD / 128, BT / 128);    // (8, 256)

    // 1) input projection: xproj = seq @ Wi^T + bi  (split-bf16 HMMA)
    split_bf16<<<nA4 / 256, 256>>>(seq, (__nv_bfloat16*)ahi, (__nv_bfloat16*)alo, nA4);
    split_bf16<<<nW4 / 256, 256>>>(Wi, (__nv_bfloat16*)bhi, (__nv_bfloat16*)blo, nW4);
    mma_gemm<<<ggrid, 256, gemm_smem>>>((const __nv_bfloat16*)ahi, (const __nv_bfloat16*)alo,
                                        (const __nv_bfloat16*)bhi, (const __nv_bfloat16*)blo,
                                        bi, (float*)xp_addr);

    // 2) recurrent scan (persistent, grid-synchronized)
    const int scan_smem = (8192 + 32768 + 32 * SP_STRIDE) * (int)sizeof(float);  // 196864
    cudaFuncSetAttribute(scan_kernel, cudaFuncAttributeMaxDynamicSharedMemorySize, scan_smem);
    scan_kernel<<<NCTA, SCAN_THREADS, scan_smem>>>((const float*)xp_addr, Wh, hidden,
                                                   (__nv_bfloat16*)ahi, (__nv_bfloat16*)alo);

    // 3) output projection: out = hidden @ Wo^T + bo (hi/lo emitted by scan)
    split_bf16<<<nW4 / 256, 256>>>(Wo, (__nv_bfloat16*)bhi, (__nv_bfloat16*)blo, nW4);
    mma_gemm<<<ggrid, 256, gemm_smem>>>((const __nv_bfloat16*)ahi, (const __nv_bfloat16*)alo,
                                        (const __nv_bfloat16*)bhi, (const __nv_bfloat16*)blo,
                                        bo, outproj);
}

// round 8
// speedup vs baseline: 2.1468x; 1.5756x over previous
#include <cuda_runtime.h>
#include <cuda_bf16.h>
#include <math.h>
#include <stdint.h>

// Problem dims (fixed by the dataset)
#define BATCH   32
#define STEPS   1024      // T
#define HD      1024      // D == H
#define BT      32768     // BATCH*STEPS rows
#define NCTA    128       // scan grid: 4 groups x 32 CTAs
#define GRP_CTAS 32

// ---------------- scratch (no allocations allowed) ----------------
__device__ float         g_xproj[(size_t)BT * HD];     // 128 MB input-proj result
__device__ unsigned int  g_bar2[4][STEPS];             // per-group per-step barrier counters
__device__ __nv_bfloat16 g_Ahi[(size_t)BT * HD];       // 64 MB
__device__ __nv_bfloat16 g_Alo[(size_t)BT * HD];       // 64 MB
__device__ __nv_bfloat16 g_Bhi[HD * HD];               // 2 MB
__device__ __nv_bfloat16 g_Blo[HD * HD];               // 2 MB
__device__ __nv_bfloat16 g_hxHi[2][BATCH * HD];        // h exchange, [b][o] bf16 hi
__device__ __nv_bfloat16 g_hxLo[2][BATCH * HD];        // h exchange, [b][o] bf16 lo

// =================================================================
// helpers (plain sm_80-era PTX only)
// =================================================================
__device__ __forceinline__ uint32_t smem_u32(const void* p) {
    uint32_t a;
    asm("{ .reg .u64 t; cvta.to.shared.u64 t, %1; cvt.u32.u64 %0, t; }" : "=r"(a) : "l"(p));
    return a;
}
__device__ __forceinline__ void cp_async16(uint32_t dst, const void* src) {
    asm volatile("cp.async.cg.shared.global [%0], [%1], 16;" :: "r"(dst), "l"(src));
}
__device__ __forceinline__ void cp_commit() {
    asm volatile("cp.async.commit_group;");
}
__device__ __forceinline__ void cp_wait1() {
    asm volatile("cp.async.wait_group 1;");
}
__device__ __forceinline__ void ldsm_x4(uint32_t* r, uint32_t addr) {
    asm volatile("ldmatrix.sync.aligned.m8n8.x4.shared.b16 {%0,%1,%2,%3}, [%4];"
                 : "=r"(r[0]), "=r"(r[1]), "=r"(r[2]), "=r"(r[3]) : "r"(addr));
}
__device__ __forceinline__ void mma_bf16(float* c, const uint32_t* a, const uint32_t* b) {
    asm volatile(
        "mma.sync.aligned.m16n8k16.row.col.f32.bf16.bf16.f32 "
        "{%0,%1,%2,%3}, {%4,%5,%6,%7}, {%8,%9}, {%0,%1,%2,%3};"
        : "+f"(c[0]), "+f"(c[1]), "+f"(c[2]), "+f"(c[3])
        : "r"(a[0]), "r"(a[1]), "r"(a[2]), "r"(a[3]), "r"(b[0]), "r"(b[1]));
}

// =================================================================
// split fp32 -> bf16 hi + bf16 lo
// =================================================================
__global__ void split_bf16(const float* __restrict__ in,
                           __nv_bfloat16* __restrict__ hi,
                           __nv_bfloat16* __restrict__ lo, int n4) {
    int i = blockIdx.x * blockDim.x + threadIdx.x;
    if (i >= n4) return;
    float4 v = ((const float4*)in)[i];
    __nv_bfloat16 h0 = __float2bfloat16(v.x);
    __nv_bfloat16 h1 = __float2bfloat16(v.y);
    __nv_bfloat16 h2 = __float2bfloat16(v.z);
    __nv_bfloat16 h3 = __float2bfloat16(v.w);
    __nv_bfloat16 l0 = __float2bfloat16(v.x - __bfloat162float(h0));
    __nv_bfloat16 l1 = __float2bfloat16(v.y - __bfloat162float(h1));
    __nv_bfloat16 l2 = __float2bfloat16(v.z - __bfloat162float(h2));
    __nv_bfloat16 l3 = __float2bfloat16(v.w - __bfloat162float(h3));
    ((__nv_bfloat162*)hi)[2 * i + 0] = __halves2bfloat162(h0, h1);
    ((__nv_bfloat162*)hi)[2 * i + 1] = __halves2bfloat162(h2, h3);
    ((__nv_bfloat162*)lo)[2 * i + 0] = __halves2bfloat162(l0, l1);
    ((__nv_bfloat162*)lo)[2 * i + 1] = __halves2bfloat162(l2, l3);
}

// =================================================================
// HMMA split-bf16 GEMM (NT)  -- unchanged (passing since R4)
// =================================================================
#define GSTAGES 3
#define TILE_B   10240
#define STAGE_B  (4 * TILE_B)
#define ROWB     80

__global__ __launch_bounds__(256)
void mma_gemm(const __nv_bfloat16* __restrict__ Ahi, const __nv_bfloat16* __restrict__ Alo,
              const __nv_bfloat16* __restrict__ Bhi, const __nv_bfloat16* __restrict__ Blo,
              const float* __restrict__ bias, float* __restrict__ C) {
    extern __shared__ char dsm[];
    const uint32_t sb = smem_u32(dsm);

    const int tid = threadIdx.x;
    const int wid = tid >> 5;
    const int lane = tid & 31;
    const int bm = blockIdx.y * 128;
    const int bn = blockIdx.x * 128;
    const int wm = (wid >> 2) * 64;
    const int wn = (wid & 3) * 32;

    const int lt  = tid >> 6;
    const int lid = tid & 63;
    const __nv_bfloat16* lsrc = (lt == 0) ? Ahi : (lt == 1) ? Alo : (lt == 2) ? Bhi : Blo;
    const int lrowb = (lt < 2) ? bm : bn;

    float acc[4][4][4];
#pragma unroll
    for (int i = 0; i < 4; i++)
#pragma unroll
        for (int j = 0; j < 4; j++)
#pragma unroll
            for (int e = 0; e < 4; e++) acc[i][j][e] = 0.f;

#pragma unroll
    for (int ps = 0; ps < GSTAGES - 1; ps++) {
        uint32_t dstb = sb + ps * STAGE_B + lt * TILE_B;
#pragma unroll
        for (int i = 0; i < 8; i++) {
            int idx = i * 64 + lid;
            int r = idx >> 2, c = idx & 3;
            cp_async16(dstb + r * ROWB + c * 16,
                       lsrc + (size_t)(lrowb + r) * HD + ps * 32 + c * 8);
        }
        cp_commit();
    }

    for (int kt = 0; kt < HD / 32; kt++) {
        cp_wait1();
        __syncthreads();

        if (kt + GSTAGES - 1 < HD / 32) {
            uint32_t dstb = sb + ((kt + GSTAGES - 1) % GSTAGES) * STAGE_B + lt * TILE_B;
#pragma unroll
            for (int i = 0; i < 8; i++) {
                int idx = i * 64 + lid;
                int r = idx >> 2, c = idx & 3;
                cp_async16(dstb + r * ROWB + c * 16,
                           lsrc + (size_t)(lrowb + r) * HD + (kt + GSTAGES - 1) * 32 + c * 8);
            }
        }
        cp_commit();

        uint32_t stg = sb + (kt % GSTAGES) * STAGE_B;
        uint32_t aBaseH = stg + 0 * TILE_B;
        uint32_t aBaseL = stg + 1 * TILE_B;
        uint32_t bBaseH = stg + 2 * TILE_B;
        uint32_t bBaseL = stg + 3 * TILE_B;

#pragma unroll
        for (int ks = 0; ks < 2; ks++) {
            uint32_t ah[4][4], al[4][4], bh[4][2], bl[4][2];
            int arow = (lane & 15);
            int acol = (lane >> 4) * 16 + ks * 32;
#pragma unroll
            for (int mt = 0; mt < 4; mt++) {
                ldsm_x4(ah[mt], aBaseH + (wm + mt * 16 + arow) * ROWB + acol);
                ldsm_x4(al[mt], aBaseL + (wm + mt * 16 + arow) * ROWB + acol);
            }
            int brow = ((lane >> 4) << 3) + (lane & 7);
            int bcol = ((lane >> 3) & 1) * 16 + ks * 32;
#pragma unroll
            for (int p = 0; p < 2; p++) {
                uint32_t t[4];
                ldsm_x4(t, bBaseH + (wn + p * 16 + brow) * ROWB + bcol);
                bh[2 * p][0] = t[0]; bh[2 * p][1] = t[1];
                bh[2 * p + 1][0] = t[2]; bh[2 * p + 1][1] = t[3];
                ldsm_x4(t, bBaseL + (wn + p * 16 + brow) * ROWB + bcol);
                bl[2 * p][0] = t[0]; bl[2 * p][1] = t[1];
                bl[2 * p + 1][0] = t[2]; bl[2 * p + 1][1] = t[3];
            }
#pragma unroll
            for (int mt = 0; mt < 4; mt++)
#pragma unroll
                for (int nt = 0; nt < 4; nt++) {
                    mma_bf16(acc[mt][nt], ah[mt], bh[nt]);
                    mma_bf16(acc[mt][nt], ah[mt], bl[nt]);
                    mma_bf16(acc[mt][nt], al[mt], bh[nt]);
                }
        }
    }

#pragma unroll
    for (int mt = 0; mt < 4; mt++) {
#pragma unroll
        for (int nt = 0; nt < 4; nt++) {
            int m0 = bm + wm + mt * 16 + (lane >> 2);
            int n0 = bn + wn + nt * 8 + (lane & 3) * 2;
            float b0 = bias[n0], b1 = bias[n0 + 1];
            float2 v0 = make_float2(acc[mt][nt][0] + b0, acc[mt][nt][1] + b1);
            float2 v1 = make_float2(acc[mt][nt][2] + b0, acc[mt][nt][3] + b1);
            *(float2*)&C[(size_t)m0 * HD + n0] = v0;
            *(float2*)&C[(size_t)(m0 + 8) * HD + n0] = v1;
        }
    }
}

// =================================================================
// Persistent recurrent scan v4: 4 groups x 32 CTAs, HMMA step GEMM
//  CTA (grp, rank): batches b0=8*grp..+7, outputs o0=32*rank..+31.
//  O[32o x 8b] = Wh[32o x 1024k] . h[8b x 1024k]^T, split-bf16,
//  Wh frags resident in registers; h exchanged as bf16 hi/lo (4 MB/step).
// =================================================================
__device__ __forceinline__ float gelu_exact(float x) {
    return 0.5f * x * (1.0f + erff(x * 0.70710678118654752f));
}

// smem byte offsets (rows padded to 2064 B = 1032 bf16 -> conflict-free ldsm)
#define SROW       2064
#define OFF_WHHI   0
#define OFF_WHLO   66048     // 32*2064
#define OFF_HHI    132096
#define OFF_HLO    148608    // +8*2064
#define OFF_PART   165120    // +8*2064
#define SPW        264       // floats per warp partial row
#define SCAN_SMEM  (OFF_PART + 16 * SPW * 4)   // 182016 B

__global__ __launch_bounds__(512)
void scan_kernel(const float* __restrict__ xproj,
                 const float* __restrict__ Wh,
                 float* __restrict__ hidden,
                 __nv_bfloat16* __restrict__ hhi,
                 __nv_bfloat16* __restrict__ hlo) {
    extern __shared__ char smem[];
    const uint32_t sb = smem_u32(smem);
    float* sPart = (float*)(smem + OFF_PART);

    const int tid  = threadIdx.x;
    const int w    = tid >> 5;          // warp 0..15: k slice [64w, 64w+64)
    const int lane = tid & 31;
    const int grp  = blockIdx.x >> 5;   // 0..3
    const int rank = blockIdx.x & 31;   // 0..31
    const int o0   = rank * 32;
    const int b0   = grp * 8;

    // ---- init: Wh rows [o0, o0+32) -> bf16 hi/lo in smem ----
    for (int i = tid; i < 8192; i += 512) {          // 32 rows x 256 float4
        int r = i >> 8, c4 = i & 255;
        float4 v = ((const float4*)Wh)[(o0 + r) * 256 + c4];
        __nv_bfloat16 h0 = __float2bfloat16(v.x);
        __nv_bfloat16 h1 = __float2bfloat16(v.y);
        __nv_bfloat16 h2 = __float2bfloat16(v.z);
        __nv_bfloat16 h3 = __float2bfloat16(v.w);
        char* dh = smem + OFF_WHHI + r * SROW + c4 * 8;
        char* dl = smem + OFF_WHLO + r * SROW + c4 * 8;
        *(__nv_bfloat162*)(dh)     = __halves2bfloat162(h0, h1);
        *(__nv_bfloat162*)(dh + 4) = __halves2bfloat162(h2, h3);
        *(__nv_bfloat162*)(dl)     = __halves2bfloat162(
            __float2bfloat16(v.x - __bfloat162float(h0)),
            __float2bfloat16(v.y - __bfloat162float(h1)));
        *(__nv_bfloat162*)(dl + 4) = __halves2bfloat162(
            __float2bfloat16(v.z - __bfloat162float(h2)),
            __float2bfloat16(v.w - __bfloat162float(h3)));
    }
    // zero h planes (h0 = 0)
    for (int i = tid; i < 8256; i += 512)            // 2*16512 B / 4
        ((uint32_t*)(smem + OFF_HHI))[i] = 0u;
    __syncthreads();

    // ---- load Wh frags into registers (resident across all steps) ----
    uint32_t aHi[2][4][4], aLo[2][4][4];
    {
        const uint32_t aBase = sb + (lane & 15) * SROW + (lane >> 4) * 16 + w * 128;
#pragma unroll
        for (int mt = 0; mt < 2; mt++)
#pragma unroll
            for (int ks = 0; ks < 4; ks++) {
                ldsm_x4(aHi[mt][ks], aBase + OFF_WHHI + mt * 16 * SROW + ks * 32);
                ldsm_x4(aLo[mt][ks], aBase + OFF_WHLO + mt * 16 * SROW + ks * 32);
            }
    }

    // reduce mapping: out = o_local*8 + b_local, 2 threads per output
    const int out   = tid >> 1;          // 0..255
    const int halfq = tid & 1;
    const int ol    = out >> 3;          // 0..31
    const int bl    = out & 7;           // 0..7
    const size_t hrow = (size_t)(b0 + bl) * STEPS;   // hidden row base (b*T)

    float xv = (halfq == 0) ? xproj[(hrow + 0) * HD + o0 + ol] : 0.f;

    const uint32_t bBase = sb + OFF_HHI + (lane & 7) * SROW + (lane >> 3) * 16 + w * 128;

    for (int s = 0; s < STEPS; s++) {
        __syncthreads();   // staged h visible; sPart free

        // ---- HMMA: acc[mt] = Wh_slice . h^T over this warp's k64 ----
        float acc[2][4];
#pragma unroll
        for (int mt = 0; mt < 2; mt++)
#pragma unroll
            for (int e = 0; e < 4; e++) acc[mt][e] = 0.f;

#pragma unroll
        for (int kp = 0; kp < 2; kp++) {
            uint32_t tH[4], tL[4];
            ldsm_x4(tH, bBase + kp * 64);
            ldsm_x4(tL, bBase + (OFF_HLO - OFF_HHI) + kp * 64);
#pragma unroll
            for (int mt = 0; mt < 2; mt++) {
                mma_bf16(acc[mt], aHi[mt][2 * kp],     tH);
                mma_bf16(acc[mt], aHi[mt][2 * kp],     tL);
                mma_bf16(acc[mt], aLo[mt][2 * kp],     tH);
                mma_bf16(acc[mt], aHi[mt][2 * kp + 1], tH + 2);
                mma_bf16(acc[mt], aHi[mt][2 * kp + 1], tL + 2);
                mma_bf16(acc[mt], aLo[mt][2 * kp + 1], tH + 2);
            }
        }

        // ---- spill per-warp partials: sPart[w][o*8+b] ----
        {
            float* pw = sPart + w * SPW;
#pragma unroll
            for (int mt = 0; mt < 2; mt++)
#pragma unroll
                for (int e = 0; e < 4; e++) {
                    int o = mt * 16 + (lane >> 2) + ((e >> 1) << 3);
                    int b = (lane & 3) * 2 + (e & 1);
                    pw[o * 8 + b] = acc[mt][e];
                }
        }
        __syncthreads();

        // ---- reduce 16 k-partials (2 thr/output), +x, GELU ----
        float v = 0.f;
#pragma unroll
        for (int q = 0; q < 8; q++)
            v += sPart[(halfq * 8 + q) * SPW + out];
        v += __shfl_xor_sync(0xFFFFFFFFu, v, 1);

        if (halfq == 0) {
            v += xv;
            float hval = gelu_exact(v);
            size_t hidx = (hrow + s) * HD + o0 + ol;
            hidden[hidx] = hval;
            __nv_bfloat16 bh = __float2bfloat16(hval);
            __nv_bfloat16 blo = __float2bfloat16(hval - __bfloat162float(bh));
            hhi[hidx] = bh;
            hlo[hidx] = blo;
            int xi = (b0 + bl) * HD + o0 + ol;
            g_hxHi[s & 1][xi] = bh;
            g_hxLo[s & 1][xi] = blo;
        }

        if (s == STEPS - 1) break;

        __threadfence();
        __syncthreads();   // all h stores fenced before arrival

        if (tid == 0) atomicAdd(&g_bar2[grp][s], 1u);   // arrive early

        float xnext = (halfq == 0) ? xproj[(hrow + s + 1) * HD + o0 + ol] : 0.f;

        if (tid == 0) {
            while (((volatile unsigned int*)g_bar2[grp])[s] < GRP_CTAS) { }
        }
        __syncthreads();

        // ---- stage h_s for this group's 8 batches (bf16 hi/lo) ----
        {
            const float4* srcH = (const float4*)(g_hxHi[s & 1] + b0 * HD);
            const float4* srcL = (const float4*)(g_hxLo[s & 1] + b0 * HD);
#pragma unroll
            for (int i = tid; i < 1024; i += 512) {   // 8 rows x 128 chunks of 16B
                int r = i >> 7, c = i & 127;
                *(float4*)(smem + OFF_HHI + r * SROW + c * 16) = __ldcg(srcH + i);
                *(float4*)(smem + OFF_HLO + r * SROW + c * 16) = __ldcg(srcL + i);
            }
        }
        xv = xnext;
    }
}

// =================================================================
extern "C" void kernel_launch(void* const* d_in, const int* in_sizes, int n_in,
                              void* d_out, int out_size) {
    const float* seq = (const float*)d_in[0];   // (B,T,D)
    const float* Wi  = (const float*)d_in[1];   // (H,D)
    const float* bi  = (const float*)d_in[2];   // (H,)
    const float* Wh  = (const float*)d_in[3];   // (H,H)
    const float* Wo  = (const float*)d_in[4];   // (H,H)
    const float* bo  = (const float*)d_in[5];   // (H,)

    float* out     = (float*)d_out;
    float* hidden  = out;                          // (B,T,H)
    float* outproj = out + (size_t)BT * HD;        // (B,T,H)

    void *xp_addr = 0, *bar_addr = 0, *ahi = 0, *alo = 0, *bhi = 0, *blo = 0;
    cudaGetSymbolAddress(&xp_addr, g_xproj);
    cudaGetSymbolAddress(&bar_addr, g_bar2);
    cudaGetSymbolAddress(&ahi, g_Ahi);
    cudaGetSymbolAddress(&alo, g_Alo);
    cudaGetSymbolAddress(&bhi, g_Bhi);
    cudaGetSymbolAddress(&blo, g_Blo);

    cudaMemsetAsync(bar_addr, 0, 4 * STEPS * sizeof(unsigned int));

    const int nA4 = BT * HD / 4;       // 8388608
    const int nW4 = HD * HD / 4;       // 262144
    const int gemm_smem = GSTAGES * STAGE_B;   // 122880
    cudaFuncSetAttribute(mma_gemm, cudaFuncAttributeMaxDynamicSharedMemorySize, gemm_smem);
    dim3 ggrid(HD / 128, BT / 128);    // (8, 256)

    // 1) input projection: xproj = seq @ Wi^T + bi  (split-bf16 HMMA)
    split_bf16<<<nA4 / 256, 256>>>(seq, (__nv_bfloat16*)ahi, (__nv_bfloat16*)alo, nA4);
    split_bf16<<<nW4 / 256, 256>>>(Wi, (__nv_bfloat16*)bhi, (__nv_bfloat16*)blo, nW4);
    mma_gemm<<<ggrid, 256, gemm_smem>>>((const __nv_bfloat16*)ahi, (const __nv_bfloat16*)alo,
                                        (const __nv_bfloat16*)bhi, (const __nv_bfloat16*)blo,
                                        bi, (float*)xp_addr);

    // 2) recurrent scan (4 independent groups, HMMA step GEMM)
    cudaFuncSetAttribute(scan_kernel, cudaFuncAttributeMaxDynamicSharedMemorySize, SCAN_SMEM);
    scan_kernel<<<NCTA, 512, SCAN_SMEM>>>((const float*)xp_addr, Wh, hidden,
                                          (__nv_bfloat16*)ahi, (__nv_bfloat16*)alo);

    // 3) output projection: out = hidden @ Wo^T + bo (hi/lo emitted by scan)
    split_bf16<<<nW4 / 256, 256>>>(Wo, (__nv_bfloat16*)bhi, (__nv_bfloat16*)blo, nW4);
    mma_gemm<<<ggrid, 256, gemm_smem>>>((const __nv_bfloat16*)ahi, (const __nv_bfloat16*)alo,
                                        (const __nv_bfloat16*)bhi, (const __nv_bfloat16*)blo,
                                        bo, outproj);
}